// round 4
// baseline (speedup 1.0000x reference)
#include <cuda_runtime.h>
#include <cuda_bf16.h>

// out[i] = sum_k targets[i,k] * temporal_bases[batch_indices[1], k] * scaling[k]
// B=8192, K=1024, T=16384. HBM-streaming GEMV: read targets once (32 MB).
// One row per warp: 8 LDG.128 in flight per thread, warp-local reduction only.

static constexpr int K = 1024;
static constexpr int THREADS = 256;           // 8 warps
static constexpr int WARPS = THREADS / 32;
static constexpr int F4_PER_LANE = K / 4 / 32; // 8 float4 per lane per row

__global__ __launch_bounds__(THREADS, 8)
void recompose_gemv_kernel(const float* __restrict__ targets,
                           const float* __restrict__ bases,
                           const float* __restrict__ scaling,
                           const int* __restrict__ batch_indices,
                           int B, int T,
                           float* __restrict__ out) {
    __shared__ float4 bs[K / 4];              // bases[t,:] * scaling  (4 KB)

    int t = batch_indices[1];
    t = min(max(t, 0), T - 1);

    // Stage bs into shared (one float4 per thread, 256*4 = 1024 = K)
    {
        const float4 b = reinterpret_cast<const float4*>(bases + (size_t)t * K)[threadIdx.x];
        const float4 s = reinterpret_cast<const float4*>(scaling)[threadIdx.x];
        bs[threadIdx.x] = make_float4(b.x * s.x, b.y * s.y, b.z * s.z, b.w * s.w);
    }
    __syncthreads();

    const int warp = threadIdx.x >> 5;
    const int lane = threadIdx.x & 31;

    // Preload this lane's bs slice into registers (shared -> reg, conflict-free)
    float4 c[F4_PER_LANE];
    #pragma unroll
    for (int j = 0; j < F4_PER_LANE; j++)
        c[j] = bs[lane + 32 * j];

    for (int row = blockIdx.x * WARPS + warp; row < B; row += gridDim.x * WARPS) {
        const float4* __restrict__ a4 =
            reinterpret_cast<const float4*>(targets + (size_t)row * K);

        float sum = 0.0f;
        #pragma unroll
        for (int j = 0; j < F4_PER_LANE; j++) {
            const float4 a = a4[lane + 32 * j];
            sum += a.x * c[j].x + a.y * c[j].y + a.z * c[j].z + a.w * c[j].w;
        }

        #pragma unroll
        for (int off = 16; off > 0; off >>= 1)
            sum += __shfl_xor_sync(0xffffffffu, sum, off);

        if (lane == 0)
            out[row] = sum;
    }
}

extern "C" void kernel_launch(void* const* d_in, const int* in_sizes, int n_in,
                              void* d_out, int out_size) {
    // Resolve inputs by unique element counts, robust to metadata ordering.
    const float* targets = nullptr;   // B*K  = 8388608
    const float* bases   = nullptr;   // T*K  = 16777216
    const float* scaling = nullptr;   // K    = 1024
    const int*   indices = nullptr;   // B    = 8192
    long targets_n = 0, bases_n = 0;

    for (int j = 0; j < n_in; j++) {
        long n = in_sizes[j];
        if (n == K) {
            scaling = (const float*)d_in[j];
        } else if (n == 8192) {
            indices = (const int*)d_in[j];
        } else if (n == 8192L * K) {
            targets = (const float*)d_in[j];
            targets_n = n;
        } else {
            bases = (const float*)d_in[j];
            bases_n = n;
        }
    }
    if (!targets || !bases || !scaling || !indices) return;

    const int B = (int)(targets_n / K);   // 8192
    const int T = (int)(bases_n / K);     // 16384
    float* out = (float*)d_out;

    const int grid = B / WARPS;           // 1024 CTAs, one row per warp
    recompose_gemv_kernel<<<grid, THREADS>>>(targets, bases, scaling, indices, B, T, out);
}

// round 5
// speedup vs baseline: 1.5055x; 1.5055x over previous
#include <cuda_runtime.h>
#include <cuda_bf16.h>

// out[i] = sum_k targets[i,k] * temporal_bases[batch_indices[1], k] * scaling[k]
// B=8192, K=1024, T=16384. HBM-streaming GEMV (32 MB of targets, read once).
// Warp-per-row, 4 rows/warp, 2-stage software pipeline: next row's loads are
// in flight while the current row is reduced/stored.

static constexpr int K = 1024;
static constexpr int THREADS = 256;            // 8 warps
static constexpr int WARPS = THREADS / 32;
static constexpr int F4 = K / 4 / 32;          // 8 float4 per lane per row
static constexpr int GRID = 256;               // 2048 warps -> 4 rows/warp @ B=8192

__device__ __forceinline__ void load_row(const float4* __restrict__ a4, float4 (&buf)[F4], int lane) {
    #pragma unroll
    for (int j = 0; j < F4; j++)
        buf[j] = a4[lane + 32 * j];
}

__device__ __forceinline__ float dot_row(const float4 (&a)[F4], const float4 (&c)[F4]) {
    float s = 0.0f;
    #pragma unroll
    for (int j = 0; j < F4; j++)
        s += a[j].x * c[j].x + a[j].y * c[j].y + a[j].z * c[j].z + a[j].w * c[j].w;
    return s;
}

__global__ __launch_bounds__(THREADS, 2)
void recompose_gemv_kernel(const float* __restrict__ targets,
                           const float* __restrict__ bases,
                           const float* __restrict__ scaling,
                           const int* __restrict__ batch_indices,
                           int B, int T,
                           float* __restrict__ out) {
    __shared__ float4 cs[K / 4];               // bases[t,:] * scaling (4 KB)

    int t = batch_indices[1];
    t = min(max(t, 0), T - 1);

    {   // stage combined vector once per CTA
        const float4 b = reinterpret_cast<const float4*>(bases + (size_t)t * K)[threadIdx.x];
        const float4 s = reinterpret_cast<const float4*>(scaling)[threadIdx.x];
        cs[threadIdx.x] = make_float4(b.x * s.x, b.y * s.y, b.z * s.z, b.w * s.w);
    }
    __syncthreads();

    const int warp = threadIdx.x >> 5;
    const int lane = threadIdx.x & 31;
    const int stride = gridDim.x * WARPS;

    // per-warp copy of c in registers (conflict-free LDS)
    float4 c[F4];
    #pragma unroll
    for (int j = 0; j < F4; j++)
        c[j] = cs[lane + 32 * j];

    int row = blockIdx.x * WARPS + warp;
    if (row >= B) return;

    float4 A0[F4], A1[F4];
    load_row(reinterpret_cast<const float4*>(targets + (size_t)row * K), A0, lane);

    while (true) {
        // ---- stage: A0 valid for `row`; prefetch row+stride into A1 ----
        int r1 = row + stride;
        if (r1 < B)
            load_row(reinterpret_cast<const float4*>(targets + (size_t)r1 * K), A1, lane);

        {
            float sum = dot_row(A0, c);
            #pragma unroll
            for (int off = 16; off > 0; off >>= 1)
                sum += __shfl_xor_sync(0xffffffffu, sum, off);
            if (lane == 0) out[row] = sum;
        }
        if (r1 >= B) break;

        // ---- stage: A1 valid for r1; prefetch r1+stride into A0 ----
        int r2 = r1 + stride;
        if (r2 < B)
            load_row(reinterpret_cast<const float4*>(targets + (size_t)r2 * K), A0, lane);

        {
            float sum = dot_row(A1, c);
            #pragma unroll
            for (int off = 16; off > 0; off >>= 1)
                sum += __shfl_xor_sync(0xffffffffu, sum, off);
            if (lane == 0) out[r1] = sum;
        }
        if (r2 >= B) break;

        row = r2;
    }
}

extern "C" void kernel_launch(void* const* d_in, const int* in_sizes, int n_in,
                              void* d_out, int out_size) {
    // Resolve inputs by unique element counts, robust to metadata ordering.
    const float* targets = nullptr;   // B*K  = 8388608
    const float* bases   = nullptr;   // T*K  = 16777216
    const float* scaling = nullptr;   // K    = 1024
    const int*   indices = nullptr;   // B    = 8192
    long targets_n = 0, bases_n = 0;

    for (int j = 0; j < n_in; j++) {
        long n = in_sizes[j];
        if (n == K) {
            scaling = (const float*)d_in[j];
        } else if (n == 8192) {
            indices = (const int*)d_in[j];
        } else if (n == 8192L * K) {
            targets = (const float*)d_in[j];
            targets_n = n;
        } else {
            bases = (const float*)d_in[j];
            bases_n = n;
        }
    }
    if (!targets || !bases || !scaling || !indices) return;

    const int B = (int)(targets_n / K);   // 8192
    const int T = (int)(bases_n / K);     // 16384
    float* out = (float*)d_out;

    recompose_gemv_kernel<<<GRID, THREADS>>>(targets, bases, scaling, indices, B, T, out);
}